// round 14
// baseline (speedup 1.0000x reference)
#include <cuda_runtime.h>
#include <cuda_bf16.h>
#include <cuda_fp16.h>
#include <cstdint>

#define N_NODES 50000
#define N_EDGES 800000
#define FIN 256
#define HF 256          // OUT_FEAT * NHEAD
#define NHEAD 4
#define ALPHA 0.2f

// ---------------- scratch (static device globals; no allocation) ----------------
__device__ __half g_hf16[(size_t)N_NODES * HF];        // 25.6 MB  h (only representation)
__device__ __nv_bfloat16 g_xhi[(size_t)N_NODES * FIN]; // 25.6 MB
__device__ __nv_bfloat16 g_xlo[(size_t)N_NODES * FIN]; // 25.6 MB
__device__ __nv_bfloat16 g_whi[FIN * HF];
__device__ __nv_bfloat16 g_wlo[FIN * HF];
__device__ float g_hl[N_NODES * NHEAD];
__device__ float g_hr[N_NODES * NHEAD];
__device__ int   g_deg[N_NODES];
__device__ int   g_off[N_NODES];
__device__ int   g_cur[N_NODES];
__device__ int   g_col[N_EDGES];

// ================= helpers =================
__device__ __forceinline__ uint32_t smem_u32(const void* p) {
    uint32_t a;
    asm("{ .reg .u64 t; cvta.to.shared.u64 t, %1; cvt.u32.u64 %0, t; }" : "=r"(a) : "l"(p));
    return a;
}
__device__ __forceinline__ void ldmat_x4(uint32_t* r, uint32_t addr) {
    asm volatile("ldmatrix.sync.aligned.m8n8.x4.shared.b16 {%0,%1,%2,%3}, [%4];"
                 : "=r"(r[0]), "=r"(r[1]), "=r"(r[2]), "=r"(r[3]) : "r"(addr));
}
__device__ __forceinline__ void ldmat_x4_t(uint32_t* r, uint32_t addr) {
    asm volatile("ldmatrix.sync.aligned.m8n8.x4.trans.shared.b16 {%0,%1,%2,%3}, [%4];"
                 : "=r"(r[0]), "=r"(r[1]), "=r"(r[2]), "=r"(r[3]) : "r"(addr));
}
__device__ __forceinline__ void mma_bf16(float* d, const uint32_t* a, uint32_t b0, uint32_t b1) {
    asm volatile(
        "mma.sync.aligned.m16n8k16.row.col.f32.bf16.bf16.f32 "
        "{%0,%1,%2,%3}, {%4,%5,%6,%7}, {%8,%9}, {%0,%1,%2,%3};"
        : "+f"(d[0]), "+f"(d[1]), "+f"(d[2]), "+f"(d[3])
        : "r"(a[0]), "r"(a[1]), "r"(a[2]), "r"(a[3]), "r"(b0), "r"(b1));
}

// ================= fp32 -> bf16 hi/lo split converters =================
__global__ void convert_x_kernel(const float* __restrict__ x) {
    const int i = blockIdx.x * blockDim.x + threadIdx.x;   // float4 index
    const int n4 = N_NODES * FIN / 4;
    if (i >= n4) return;
    const float4 v = *(const float4*)(x + i * 4);
    __nv_bfloat162 h0, h1, l0, l1;
    h0.x = __float2bfloat16(v.x); h0.y = __float2bfloat16(v.y);
    h1.x = __float2bfloat16(v.z); h1.y = __float2bfloat16(v.w);
    l0.x = __float2bfloat16(v.x - __bfloat162float(h0.x));
    l0.y = __float2bfloat16(v.y - __bfloat162float(h0.y));
    l1.x = __float2bfloat16(v.z - __bfloat162float(h1.x));
    l1.y = __float2bfloat16(v.w - __bfloat162float(h1.y));
    uint2 hv, lv;
    hv.x = *(uint32_t*)&h0; hv.y = *(uint32_t*)&h1;
    lv.x = *(uint32_t*)&l0; lv.y = *(uint32_t*)&l1;
    *(uint2*)(g_xhi + i * 4) = hv;
    *(uint2*)(g_xlo + i * 4) = lv;
}
__global__ void convert_w_kernel(const float* __restrict__ w) {
    const int i = blockIdx.x * blockDim.x + threadIdx.x;
    const int n4 = FIN * HF / 4;
    if (i >= n4) return;
    const float4 v = *(const float4*)(w + i * 4);
    __nv_bfloat162 h0, h1, l0, l1;
    h0.x = __float2bfloat16(v.x); h0.y = __float2bfloat16(v.y);
    h1.x = __float2bfloat16(v.z); h1.y = __float2bfloat16(v.w);
    l0.x = __float2bfloat16(v.x - __bfloat162float(h0.x));
    l0.y = __float2bfloat16(v.y - __bfloat162float(h0.y));
    l1.x = __float2bfloat16(v.z - __bfloat162float(h1.x));
    l1.y = __float2bfloat16(v.w - __bfloat162float(h1.y));
    uint2 hv, lv;
    hv.x = *(uint32_t*)&h0; hv.y = *(uint32_t*)&h1;
    lv.x = *(uint32_t*)&l0; lv.y = *(uint32_t*)&l1;
    *(uint2*)(g_whi + i * 4) = hv;
    *(uint2*)(g_wlo + i * 4) = lv;
}

// ================= GEMM: h = x @ W via split-bf16 mma.sync =================
// CTA tile 128(m) x 128(n), K chunks of 64. 8 warps = 4(m) x 2(n), warp tile 32x64.
// Fused epilogue: fp16 h stores + hl/hr (warp's 64 cols = one head; shfl reduce).
#define AS_STRIDE 72
#define BS_STRIDE 136
#define A_BUF (128 * AS_STRIDE)
#define B_BUF (64 * BS_STRIDE)
#define SMEM_ELEMS (2 * (A_BUF + B_BUF))
#define SMEM_BYTES (SMEM_ELEMS * 2)  // 71680 B

__global__ void __launch_bounds__(256, 2) gemm_mma_kernel(const float* __restrict__ a_l,
                                                          const float* __restrict__ a_r) {
    extern __shared__ __nv_bfloat16 sm[];
    __nv_bfloat16* Ah = sm;
    __nv_bfloat16* Al = sm + A_BUF;
    __nv_bfloat16* Bh = sm + 2 * A_BUF;
    __nv_bfloat16* Bl = sm + 2 * A_BUF + B_BUF;

    const int tid = threadIdx.x;
    const int lane = tid & 31;
    const int warp = tid >> 5;
    const int warp_m = warp & 3;
    const int warp_n = warp >> 2;
    const int rowBase = blockIdx.y * 128;
    const int colBase = blockIdx.x * 128;

    float acc[2][8][4];
#pragma unroll
    for (int i = 0; i < 2; i++)
#pragma unroll
        for (int j = 0; j < 8; j++)
#pragma unroll
            for (int k = 0; k < 4; k++) acc[i][j][k] = 0.0f;

    const uint32_t sbase = smem_u32(sm);
    const uint32_t ah_b = sbase;
    const uint32_t al_b = sbase + A_BUF * 2;
    const uint32_t bh_b = sbase + 4 * A_BUF;
    const uint32_t bl_b = sbase + 4 * A_BUF + B_BUF * 2;

    const uint4 zero4 = make_uint4(0u, 0u, 0u, 0u);

    for (int chunk = 0; chunk < 4; chunk++) {
        const int k0 = chunk * 64;
#pragma unroll
        for (int i = 0; i < 4; i++) {
            const int p = tid + i * 256;
            const int row = p >> 3, c = p & 7;
            const int gr = rowBase + row;
            uint4 hv = zero4, lv = zero4;
            if (gr < N_NODES) {
                const size_t goff = (size_t)gr * FIN + k0 + c * 8;
                hv = *(const uint4*)(g_xhi + goff);
                lv = *(const uint4*)(g_xlo + goff);
            }
            *(uint4*)(Ah + row * AS_STRIDE + c * 8) = hv;
            *(uint4*)(Al + row * AS_STRIDE + c * 8) = lv;
        }
#pragma unroll
        for (int i = 0; i < 4; i++) {
            const int p = tid + i * 256;
            const int kk = p >> 4, c = p & 15;
            const size_t goff = (size_t)(k0 + kk) * HF + colBase + c * 8;
            *(uint4*)(Bh + kk * BS_STRIDE + c * 8) = *(const uint4*)(g_whi + goff);
            *(uint4*)(Bl + kk * BS_STRIDE + c * 8) = *(const uint4*)(g_wlo + goff);
        }
        __syncthreads();

#pragma unroll
        for (int ks = 0; ks < 4; ks++) {
            const int kk = ks * 16;
            uint32_t ahf[2][4], alf[2][4];
#pragma unroll
            for (int mt = 0; mt < 2; mt++) {
                const int r = warp_m * 32 + mt * 16 + (lane & 15);
                const uint32_t off = (uint32_t)(r * AS_STRIDE + kk + (lane >> 4) * 8) * 2;
                ldmat_x4(ahf[mt], ah_b + off);
                ldmat_x4(alf[mt], al_b + off);
            }
            uint32_t bhf[4][4], blf[4][4];
#pragma unroll
            for (int nb = 0; nb < 4; nb++) {
                const int r = kk + (lane & 15);
                const int n = warp_n * 64 + nb * 16 + (lane >> 4) * 8;
                const uint32_t off = (uint32_t)(r * BS_STRIDE + n) * 2;
                ldmat_x4_t(bhf[nb], bh_b + off);
                ldmat_x4_t(blf[nb], bl_b + off);
            }
#pragma unroll
            for (int mt = 0; mt < 2; mt++)
#pragma unroll
                for (int nt = 0; nt < 8; nt++) {
                    const int nb = nt >> 1, hh = (nt & 1) * 2;
                    mma_bf16(acc[mt][nt], ahf[mt], bhf[nb][hh], bhf[nb][hh + 1]);
                    mma_bf16(acc[mt][nt], ahf[mt], blf[nb][hh], blf[nb][hh + 1]);
                    mma_bf16(acc[mt][nt], alf[mt], bhf[nb][hh], bhf[nb][hh + 1]);
                }
        }
        __syncthreads();
    }

    const int g = lane >> 2, t = lane & 3;
    const int head = (colBase >> 6) + warp_n;     // this warp's 64 cols = one head

#pragma unroll
    for (int mt = 0; mt < 2; mt++) {
#pragma unroll
        for (int rh = 0; rh < 2; rh++) {
            const int r = rowBase + warp_m * 32 + mt * 16 + rh * 8 + g;
            float sl = 0.f, sr = 0.f;
#pragma unroll
            for (int nt = 0; nt < 8; nt++) {
                const int col = colBase + warp_n * 64 + nt * 8 + t * 2;
                const float v0 = acc[mt][nt][rh * 2 + 0];
                const float v1 = acc[mt][nt][rh * 2 + 1];
                if (r < N_NODES)
                    *(__half2*)(g_hf16 + (size_t)r * HF + col) = __floats2half2_rn(v0, v1);
                sl = fmaf(v0, a_l[col], sl); sl = fmaf(v1, a_l[col + 1], sl);
                sr = fmaf(v0, a_r[col], sr); sr = fmaf(v1, a_r[col + 1], sr);
            }
            sl += __shfl_xor_sync(0xffffffffu, sl, 1);
            sl += __shfl_xor_sync(0xffffffffu, sl, 2);
            sr += __shfl_xor_sync(0xffffffffu, sr, 1);
            sr += __shfl_xor_sync(0xffffffffu, sr, 2);
            if (t == 0 && r < N_NODES) {
                g_hl[r * NHEAD + head] = sl;
                g_hr[r * NHEAD + head] = sr;
            }
        }
    }
}

// ---------------- CSR build ----------------
__global__ void zero_deg_kernel() {
    int i = blockIdx.x * blockDim.x + threadIdx.x;
    if (i < N_NODES) g_deg[i] = 0;
}
__global__ void hist_kernel(const int* __restrict__ edge) {
    int i = blockIdx.x * blockDim.x + threadIdx.x;
    if (i < N_EDGES) atomicAdd(&g_deg[edge[i]], 1);
}
__global__ void scan_kernel() {
    __shared__ int partial[1024];
    const int t = threadIdx.x;
    const int CH = (N_NODES + 1023) / 1024;
    int beg = t * CH;
    int end = beg + CH; if (end > N_NODES) end = N_NODES;
    int s = 0;
    for (int i = beg; i < end; i++) s += g_deg[i];
    partial[t] = s;
    __syncthreads();
    for (int off = 1; off < 1024; off <<= 1) {
        int v = (t >= off) ? partial[t - off] : 0;
        __syncthreads();
        partial[t] += v;
        __syncthreads();
    }
    int run = (t == 0) ? 0 : partial[t - 1];
    for (int i = beg; i < end; i++) {
        g_off[i] = run;
        g_cur[i] = run;
        run += g_deg[i];
    }
}
__global__ void scatter_kernel(const int* __restrict__ edge) {
    int i = blockIdx.x * blockDim.x + threadIdx.x;
    if (i < N_EDGES) {
        int r = edge[i];
        int c = edge[N_EDGES + i];
        int pos = atomicAdd(&g_cur[r], 1);
        g_col[pos] = c;
    }
}

// ---------------- aggregation: 2 warps/node, fp16 gathers, 4-edge batch ----------------
__global__ void aggregate_kernel(float* __restrict__ out) {
    const int gw = (blockIdx.x * blockDim.x + threadIdx.x) >> 5;
    const int node = gw >> 1;
    if (node >= N_NODES) return;
    const int half = gw & 1;
    const int lane = threadIdx.x & 31;
    const int fbase = half * 128 + lane * 4;      // this lane's 4 features
    const int head = fbase >> 6;                  // 0..3 (16 lanes per head)

    const int start = g_off[node];
    const int d = g_deg[node];
    const float hlh = g_hl[node * NHEAD + head];

    float denom = 0.f;
    float a0 = 0.f, a1 = 0.f, a2 = 0.f, a3 = 0.f;

    int k = 0;
    for (; k + 4 <= d; k += 4) {
        const int c0 = g_col[start + k + 0];
        const int c1 = g_col[start + k + 1];
        const int c2 = g_col[start + k + 2];
        const int c3 = g_col[start + k + 3];
        // 4 independent hr gathers + 4 independent fp16 h gathers in flight
        float e0 = hlh + __ldg(g_hr + (size_t)c0 * NHEAD + head);
        float e1 = hlh + __ldg(g_hr + (size_t)c1 * NHEAD + head);
        float e2 = hlh + __ldg(g_hr + (size_t)c2 * NHEAD + head);
        float e3 = hlh + __ldg(g_hr + (size_t)c3 * NHEAD + head);
        const uint2 r0 = *(const uint2*)(g_hf16 + (size_t)c0 * HF + fbase);
        const uint2 r1 = *(const uint2*)(g_hf16 + (size_t)c1 * HF + fbase);
        const uint2 r2 = *(const uint2*)(g_hf16 + (size_t)c2 * HF + fbase);
        const uint2 r3 = *(const uint2*)(g_hf16 + (size_t)c3 * HF + fbase);
        e0 = e0 > 0.f ? e0 : ALPHA * e0;
        e1 = e1 > 0.f ? e1 : ALPHA * e1;
        e2 = e2 > 0.f ? e2 : ALPHA * e2;
        e3 = e3 > 0.f ? e3 : ALPHA * e3;
        const float w0 = __expf(e0), w1 = __expf(e1), w2 = __expf(e2), w3 = __expf(e3);
        denom += (w0 + w1) + (w2 + w3);
        const float2 u00 = __half22float2(*(const __half2*)&r0.x);
        const float2 u01 = __half22float2(*(const __half2*)&r0.y);
        const float2 u10 = __half22float2(*(const __half2*)&r1.x);
        const float2 u11 = __half22float2(*(const __half2*)&r1.y);
        const float2 u20 = __half22float2(*(const __half2*)&r2.x);
        const float2 u21 = __half22float2(*(const __half2*)&r2.y);
        const float2 u30 = __half22float2(*(const __half2*)&r3.x);
        const float2 u31 = __half22float2(*(const __half2*)&r3.y);
        a0 = fmaf(w0, u00.x, a0); a1 = fmaf(w0, u00.y, a1);
        a2 = fmaf(w0, u01.x, a2); a3 = fmaf(w0, u01.y, a3);
        a0 = fmaf(w1, u10.x, a0); a1 = fmaf(w1, u10.y, a1);
        a2 = fmaf(w1, u11.x, a2); a3 = fmaf(w1, u11.y, a3);
        a0 = fmaf(w2, u20.x, a0); a1 = fmaf(w2, u20.y, a1);
        a2 = fmaf(w2, u21.x, a2); a3 = fmaf(w2, u21.y, a3);
        a0 = fmaf(w3, u30.x, a0); a1 = fmaf(w3, u30.y, a1);
        a2 = fmaf(w3, u31.x, a2); a3 = fmaf(w3, u31.y, a3);
    }
    for (; k < d; k++) {
        const int c = g_col[start + k];
        float e = hlh + __ldg(g_hr + (size_t)c * NHEAD + head);
        e = e > 0.f ? e : ALPHA * e;
        const float w = __expf(e);
        denom += w;
        const uint2 r = *(const uint2*)(g_hf16 + (size_t)c * HF + fbase);
        const float2 u0 = __half22float2(*(const __half2*)&r.x);
        const float2 u1 = __half22float2(*(const __half2*)&r.y);
        a0 = fmaf(w, u0.x, a0); a1 = fmaf(w, u0.y, a1);
        a2 = fmaf(w, u1.x, a2); a3 = fmaf(w, u1.y, a3);
    }
    const float inv = 1.0f / fmaxf(denom, 1e-16f);
    *(float4*)(out + (size_t)node * HF + fbase) =
        make_float4(a0 * inv, a1 * inv, a2 * inv, a3 * inv);
}

// ---------------- launch: fork CSR build onto a side stream ----------------
static cudaStream_t s_sideStream = nullptr;
static cudaEvent_t  s_evFork = nullptr;
static cudaEvent_t  s_evJoin = nullptr;

extern "C" void kernel_launch(void* const* d_in, const int* in_sizes, int n_in,
                              void* d_out, int out_size) {
    const float* x    = (const float*)d_in[0];
    const int*   edge = (const int*)d_in[1];     // int32: [2, E] (rows; cols)
    const float* W    = (const float*)d_in[2];
    const float* a_l  = (const float*)d_in[3];
    const float* a_r  = (const float*)d_in[4];
    float* out = (float*)d_out;

    if (s_sideStream == nullptr) {               // first call is outside graph capture
        cudaStreamCreateWithFlags(&s_sideStream, cudaStreamNonBlocking);
        cudaEventCreateWithFlags(&s_evFork, cudaEventDisableTiming);
        cudaEventCreateWithFlags(&s_evJoin, cudaEventDisableTiming);
    }

    // fork: side stream builds the CSR (independent of GEMM chain)
    cudaEventRecord(s_evFork, 0);
    cudaStreamWaitEvent(s_sideStream, s_evFork, 0);
    zero_deg_kernel<<<(N_NODES + 255) / 256, 256, 0, s_sideStream>>>();
    hist_kernel<<<(N_EDGES + 255) / 256, 256, 0, s_sideStream>>>(edge);
    scan_kernel<<<1, 1024, 0, s_sideStream>>>();
    scatter_kernel<<<(N_EDGES + 255) / 256, 256, 0, s_sideStream>>>(edge);
    cudaEventRecord(s_evJoin, s_sideStream);

    // main stream: convert -> GEMM (fused hl/hr + fp16 h)
    convert_x_kernel<<<(N_NODES * FIN / 4 + 255) / 256, 256>>>(x);
    convert_w_kernel<<<(FIN * HF / 4 + 255) / 256, 256>>>(W);
    cudaFuncSetAttribute(gemm_mma_kernel, cudaFuncAttributeMaxDynamicSharedMemorySize, SMEM_BYTES);
    dim3 ggrid(HF / 128, (N_NODES + 127) / 128);     // (2, 391)
    gemm_mma_kernel<<<ggrid, 256, SMEM_BYTES>>>(a_l, a_r);

    // join, then aggregate
    cudaStreamWaitEvent(0, s_evJoin, 0);
    aggregate_kernel<<<(N_NODES * 2 * 32 + 255) / 256, 256>>>(out);
}

// round 15
// speedup vs baseline: 1.0159x; 1.0159x over previous
#include <cuda_runtime.h>
#include <cuda_bf16.h>
#include <cuda_fp16.h>
#include <cstdint>

#define N_NODES 50000
#define N_EDGES 800000
#define FIN 256
#define HF 256          // OUT_FEAT * NHEAD
#define NHEAD 4
#define ALPHA 0.2f

// ---------------- scratch (static device globals; no allocation) ----------------
__device__ __half g_hf16[(size_t)N_NODES * HF];        // 25.6 MB  h (only representation)
__device__ __nv_bfloat16 g_xhi[(size_t)N_NODES * FIN]; // 25.6 MB
__device__ __nv_bfloat16 g_xlo[(size_t)N_NODES * FIN]; // 25.6 MB
__device__ __nv_bfloat16 g_whi[FIN * HF];
__device__ __nv_bfloat16 g_wlo[FIN * HF];
__device__ float g_hl[N_NODES * NHEAD];
__device__ float g_hr[N_NODES * NHEAD];
__device__ int   g_deg[N_NODES];
__device__ int   g_off[N_NODES];
__device__ int   g_cur[N_NODES];
__device__ int   g_col[N_EDGES];

// ================= helpers =================
__device__ __forceinline__ uint32_t smem_u32(const void* p) {
    uint32_t a;
    asm("{ .reg .u64 t; cvta.to.shared.u64 t, %1; cvt.u32.u64 %0, t; }" : "=r"(a) : "l"(p));
    return a;
}
__device__ __forceinline__ void ldmat_x4(uint32_t* r, uint32_t addr) {
    asm volatile("ldmatrix.sync.aligned.m8n8.x4.shared.b16 {%0,%1,%2,%3}, [%4];"
                 : "=r"(r[0]), "=r"(r[1]), "=r"(r[2]), "=r"(r[3]) : "r"(addr));
}
__device__ __forceinline__ void ldmat_x4_t(uint32_t* r, uint32_t addr) {
    asm volatile("ldmatrix.sync.aligned.m8n8.x4.trans.shared.b16 {%0,%1,%2,%3}, [%4];"
                 : "=r"(r[0]), "=r"(r[1]), "=r"(r[2]), "=r"(r[3]) : "r"(addr));
}
__device__ __forceinline__ void mma_bf16(float* d, const uint32_t* a, uint32_t b0, uint32_t b1) {
    asm volatile(
        "mma.sync.aligned.m16n8k16.row.col.f32.bf16.bf16.f32 "
        "{%0,%1,%2,%3}, {%4,%5,%6,%7}, {%8,%9}, {%0,%1,%2,%3};"
        : "+f"(d[0]), "+f"(d[1]), "+f"(d[2]), "+f"(d[3])
        : "r"(a[0]), "r"(a[1]), "r"(a[2]), "r"(a[3]), "r"(b0), "r"(b1));
}
__device__ __forceinline__ void cp16(uint32_t dst, const void* src, uint32_t srcsize) {
    asm volatile("cp.async.cg.shared.global [%0], [%1], 16, %2;"
                 :: "r"(dst), "l"(src), "r"(srcsize));
}
#define CP_COMMIT() asm volatile("cp.async.commit_group;" ::: "memory")
#define CP_WAIT(N)  asm volatile("cp.async.wait_group %0;" :: "n"(N) : "memory")

// ================= fp32 -> bf16 hi/lo split converters =================
__global__ void convert_x_kernel(const float* __restrict__ x) {
    const int i = blockIdx.x * blockDim.x + threadIdx.x;   // float4 index
    const int n4 = N_NODES * FIN / 4;
    if (i >= n4) return;
    const float4 v = *(const float4*)(x + i * 4);
    __nv_bfloat162 h0, h1, l0, l1;
    h0.x = __float2bfloat16(v.x); h0.y = __float2bfloat16(v.y);
    h1.x = __float2bfloat16(v.z); h1.y = __float2bfloat16(v.w);
    l0.x = __float2bfloat16(v.x - __bfloat162float(h0.x));
    l0.y = __float2bfloat16(v.y - __bfloat162float(h0.y));
    l1.x = __float2bfloat16(v.z - __bfloat162float(h1.x));
    l1.y = __float2bfloat16(v.w - __bfloat162float(h1.y));
    uint2 hv, lv;
    hv.x = *(uint32_t*)&h0; hv.y = *(uint32_t*)&h1;
    lv.x = *(uint32_t*)&l0; lv.y = *(uint32_t*)&l1;
    *(uint2*)(g_xhi + i * 4) = hv;
    *(uint2*)(g_xlo + i * 4) = lv;
}
__global__ void convert_w_kernel(const float* __restrict__ w) {
    const int i = blockIdx.x * blockDim.x + threadIdx.x;
    const int n4 = FIN * HF / 4;
    if (i >= n4) return;
    const float4 v = *(const float4*)(w + i * 4);
    __nv_bfloat162 h0, h1, l0, l1;
    h0.x = __float2bfloat16(v.x); h0.y = __float2bfloat16(v.y);
    h1.x = __float2bfloat16(v.z); h1.y = __float2bfloat16(v.w);
    l0.x = __float2bfloat16(v.x - __bfloat162float(h0.x));
    l0.y = __float2bfloat16(v.y - __bfloat162float(h0.y));
    l1.x = __float2bfloat16(v.z - __bfloat162float(h1.x));
    l1.y = __float2bfloat16(v.w - __bfloat162float(h1.y));
    uint2 hv, lv;
    hv.x = *(uint32_t*)&h0; hv.y = *(uint32_t*)&h1;
    lv.x = *(uint32_t*)&l0; lv.y = *(uint32_t*)&l1;
    *(uint2*)(g_whi + i * 4) = hv;
    *(uint2*)(g_wlo + i * 4) = lv;
}

// ================= GEMM: h = x @ W via split-bf16 mma.sync + cp.async pipeline ====
// CTA tile 128(m) x 128(n). K in 8 chunks of 32, double-buffered via cp.async.
// 8 warps = 4(m) x 2(n), warp tile 32x64.
// Fused epilogue: fp16 h stores + hl/hr (warp's 64 cols = one head; shfl reduce).
#define NCHUNK 8
#define BK 32
#define AS_STRIDE 40                 // 32 + 8 pad (bf16 elems per A row)
#define BS_STRIDE 136                // 128 + 8 pad
#define A_BUF (128 * AS_STRIDE)      // 5120 elems
#define B_BUF (BK * BS_STRIDE)       // 4352 elems
#define SET_ELEMS (2 * (A_BUF + B_BUF))  // hi+lo set: 18944 elems
#define SMEM_BYTES (2 * SET_ELEMS * 2)   // two sets: 75776 B

__device__ __forceinline__ void gemm_issue_loads(int chunk, int set, uint32_t sbase,
                                                 int rowBase, int colBase, int tid) {
    const int k0 = chunk * BK;
    const uint32_t so = sbase + (uint32_t)set * SET_ELEMS * 2;
#pragma unroll
    for (int i = 0; i < 2; i++) {
        const int p = tid + i * 256;          // 0..511
        const int row = p >> 2, seg = p & 3;  // A: 128 rows x 4 16B-segs
        const int gr = rowBase + row;
        const uint32_t ok = (gr < N_NODES) ? 16u : 0u;
        const size_t goff = (size_t)gr * FIN + k0 + seg * 8;
        const uint32_t d = so + (uint32_t)(row * AS_STRIDE + seg * 8) * 2;
        cp16(d, g_xhi + goff, ok);
        cp16(d + A_BUF * 2, g_xlo + goff, ok);
    }
#pragma unroll
    for (int i = 0; i < 2; i++) {
        const int p = tid + i * 256;          // 0..511
        const int kk = p >> 4, seg = p & 15;  // B: 32 k-rows x 16 16B-segs
        const size_t goff = (size_t)(k0 + kk) * HF + colBase + seg * 8;
        const uint32_t d = so + (uint32_t)(2 * A_BUF + kk * BS_STRIDE + seg * 8) * 2;
        cp16(d, g_whi + goff, 16u);
        cp16(d + B_BUF * 2, g_wlo + goff, 16u);
    }
    CP_COMMIT();
}

__global__ void __launch_bounds__(256, 2) gemm_mma_kernel(const float* __restrict__ a_l,
                                                          const float* __restrict__ a_r) {
    extern __shared__ __nv_bfloat16 sm[];
    const int tid = threadIdx.x;
    const int lane = tid & 31;
    const int warp = tid >> 5;
    const int warp_m = warp & 3;
    const int warp_n = warp >> 2;
    const int rowBase = blockIdx.y * 128;
    const int colBase = blockIdx.x * 128;

    float acc[2][8][4];
#pragma unroll
    for (int i = 0; i < 2; i++)
#pragma unroll
        for (int j = 0; j < 8; j++)
#pragma unroll
            for (int k = 0; k < 4; k++) acc[i][j][k] = 0.0f;

    const uint32_t sbase = smem_u32(sm);

    gemm_issue_loads(0, 0, sbase, rowBase, colBase, tid);

    for (int c = 0; c < NCHUNK; c++) {
        const int set = c & 1;
        if (c + 1 < NCHUNK) {
            gemm_issue_loads(c + 1, set ^ 1, sbase, rowBase, colBase, tid);
            CP_WAIT(1);
        } else {
            CP_WAIT(0);
        }
        __syncthreads();

        const uint32_t so = sbase + (uint32_t)set * SET_ELEMS * 2;
        const uint32_t ah_b = so;
        const uint32_t al_b = so + A_BUF * 2;
        const uint32_t bh_b = so + 4 * A_BUF;
        const uint32_t bl_b = so + 4 * A_BUF + B_BUF * 2;

#pragma unroll
        for (int ks = 0; ks < 2; ks++) {
            const int kk = ks * 16;
            uint32_t ahf[2][4], alf[2][4];
#pragma unroll
            for (int mt = 0; mt < 2; mt++) {
                const int r = warp_m * 32 + mt * 16 + (lane & 15);
                const uint32_t off = (uint32_t)(r * AS_STRIDE + kk + (lane >> 4) * 8) * 2;
                ldmat_x4(ahf[mt], ah_b + off);
                ldmat_x4(alf[mt], al_b + off);
            }
            uint32_t bhf[4][4], blf[4][4];
#pragma unroll
            for (int nb = 0; nb < 4; nb++) {
                const int r = kk + (lane & 15);
                const int n = warp_n * 64 + nb * 16 + (lane >> 4) * 8;
                const uint32_t off = (uint32_t)(r * BS_STRIDE + n) * 2;
                ldmat_x4_t(bhf[nb], bh_b + off);
                ldmat_x4_t(blf[nb], bl_b + off);
            }
#pragma unroll
            for (int mt = 0; mt < 2; mt++)
#pragma unroll
                for (int nt = 0; nt < 8; nt++) {
                    const int nb = nt >> 1, hh = (nt & 1) * 2;
                    mma_bf16(acc[mt][nt], ahf[mt], bhf[nb][hh], bhf[nb][hh + 1]);
                    mma_bf16(acc[mt][nt], ahf[mt], blf[nb][hh], blf[nb][hh + 1]);
                    mma_bf16(acc[mt][nt], alf[mt], bhf[nb][hh], bhf[nb][hh + 1]);
                }
        }
        __syncthreads();
    }

    const int g = lane >> 2, t = lane & 3;
    const int head = (colBase >> 6) + warp_n;     // this warp's 64 cols = one head

#pragma unroll
    for (int mt = 0; mt < 2; mt++) {
#pragma unroll
        for (int rh = 0; rh < 2; rh++) {
            const int r = rowBase + warp_m * 32 + mt * 16 + rh * 8 + g;
            float sl = 0.f, sr = 0.f;
#pragma unroll
            for (int nt = 0; nt < 8; nt++) {
                const int col = colBase + warp_n * 64 + nt * 8 + t * 2;
                const float v0 = acc[mt][nt][rh * 2 + 0];
                const float v1 = acc[mt][nt][rh * 2 + 1];
                if (r < N_NODES)
                    *(__half2*)(g_hf16 + (size_t)r * HF + col) = __floats2half2_rn(v0, v1);
                sl = fmaf(v0, a_l[col], sl); sl = fmaf(v1, a_l[col + 1], sl);
                sr = fmaf(v0, a_r[col], sr); sr = fmaf(v1, a_r[col + 1], sr);
            }
            sl += __shfl_xor_sync(0xffffffffu, sl, 1);
            sl += __shfl_xor_sync(0xffffffffu, sl, 2);
            sr += __shfl_xor_sync(0xffffffffu, sr, 1);
            sr += __shfl_xor_sync(0xffffffffu, sr, 2);
            if (t == 0 && r < N_NODES) {
                g_hl[r * NHEAD + head] = sl;
                g_hr[r * NHEAD + head] = sr;
            }
        }
    }
}

// ---------------- CSR build ----------------
__global__ void zero_deg_kernel() {
    int i = blockIdx.x * blockDim.x + threadIdx.x;
    if (i < N_NODES) g_deg[i] = 0;
}
__global__ void hist_kernel(const int* __restrict__ edge) {
    int i = blockIdx.x * blockDim.x + threadIdx.x;
    if (i < N_EDGES) atomicAdd(&g_deg[edge[i]], 1);
}
__global__ void scan_kernel() {
    __shared__ int partial[1024];
    const int t = threadIdx.x;
    const int CH = (N_NODES + 1023) / 1024;
    int beg = t * CH;
    int end = beg + CH; if (end > N_NODES) end = N_NODES;
    int s = 0;
    for (int i = beg; i < end; i++) s += g_deg[i];
    partial[t] = s;
    __syncthreads();
    for (int off = 1; off < 1024; off <<= 1) {
        int v = (t >= off) ? partial[t - off] : 0;
        __syncthreads();
        partial[t] += v;
        __syncthreads();
    }
    int run = (t == 0) ? 0 : partial[t - 1];
    for (int i = beg; i < end; i++) {
        g_off[i] = run;
        g_cur[i] = run;
        run += g_deg[i];
    }
}
__global__ void scatter_kernel(const int* __restrict__ edge) {
    int i = blockIdx.x * blockDim.x + threadIdx.x;
    if (i < N_EDGES) {
        int r = edge[i];
        int c = edge[N_EDGES + i];
        int pos = atomicAdd(&g_cur[r], 1);
        g_col[pos] = c;
    }
}

// ---------------- aggregation: 2 warps/node, fp16 gathers, 2-edge batch (R13) ----------------
__global__ void aggregate_kernel(float* __restrict__ out) {
    const int gw = (blockIdx.x * blockDim.x + threadIdx.x) >> 5;
    const int node = gw >> 1;
    if (node >= N_NODES) return;
    const int half = gw & 1;
    const int lane = threadIdx.x & 31;
    const int fbase = half * 128 + lane * 4;      // this lane's 4 features
    const int head = fbase >> 6;                  // 0..3 (16 lanes per head)

    const int start = g_off[node];
    const int d = g_deg[node];
    const float hlh = g_hl[node * NHEAD + head];

    float denom = 0.f;
    float a0 = 0.f, a1 = 0.f, a2 = 0.f, a3 = 0.f;

    int k = 0;
    for (; k + 2 <= d; k += 2) {
        const int c0 = g_col[start + k + 0];
        const int c1 = g_col[start + k + 1];
        float e0 = hlh + __ldg(g_hr + (size_t)c0 * NHEAD + head);
        float e1 = hlh + __ldg(g_hr + (size_t)c1 * NHEAD + head);
        e0 = e0 > 0.f ? e0 : ALPHA * e0;
        e1 = e1 > 0.f ? e1 : ALPHA * e1;
        const float w0 = __expf(e0), w1 = __expf(e1);
        denom += w0 + w1;
        const uint2 r0 = *(const uint2*)(g_hf16 + (size_t)c0 * HF + fbase);
        const uint2 r1 = *(const uint2*)(g_hf16 + (size_t)c1 * HF + fbase);
        const float2 u0 = __half22float2(*(const __half2*)&r0.x);
        const float2 u1 = __half22float2(*(const __half2*)&r0.y);
        const float2 u2 = __half22float2(*(const __half2*)&r1.x);
        const float2 u3 = __half22float2(*(const __half2*)&r1.y);
        a0 = fmaf(w0, u0.x, a0); a1 = fmaf(w0, u0.y, a1);
        a2 = fmaf(w0, u1.x, a2); a3 = fmaf(w0, u1.y, a3);
        a0 = fmaf(w1, u2.x, a0); a1 = fmaf(w1, u2.y, a1);
        a2 = fmaf(w1, u3.x, a2); a3 = fmaf(w1, u3.y, a3);
    }
    if (k < d) {
        const int c = g_col[start + k];
        float e = hlh + __ldg(g_hr + (size_t)c * NHEAD + head);
        e = e > 0.f ? e : ALPHA * e;
        const float w = __expf(e);
        denom += w;
        const uint2 r = *(const uint2*)(g_hf16 + (size_t)c * HF + fbase);
        const float2 u0 = __half22float2(*(const __half2*)&r.x);
        const float2 u1 = __half22float2(*(const __half2*)&r.y);
        a0 = fmaf(w, u0.x, a0); a1 = fmaf(w, u0.y, a1);
        a2 = fmaf(w, u1.x, a2); a3 = fmaf(w, u1.y, a3);
    }
    const float inv = 1.0f / fmaxf(denom, 1e-16f);
    *(float4*)(out + (size_t)node * HF + fbase) =
        make_float4(a0 * inv, a1 * inv, a2 * inv, a3 * inv);
}

// ---------------- launch: fork CSR build onto a side stream ----------------
static cudaStream_t s_sideStream = nullptr;
static cudaEvent_t  s_evFork = nullptr;
static cudaEvent_t  s_evJoin = nullptr;

extern "C" void kernel_launch(void* const* d_in, const int* in_sizes, int n_in,
                              void* d_out, int out_size) {
    const float* x    = (const float*)d_in[0];
    const int*   edge = (const int*)d_in[1];     // int32: [2, E] (rows; cols)
    const float* W    = (const float*)d_in[2];
    const float* a_l  = (const float*)d_in[3];
    const float* a_r  = (const float*)d_in[4];
    float* out = (float*)d_out;

    if (s_sideStream == nullptr) {               // first call is outside graph capture
        cudaStreamCreateWithFlags(&s_sideStream, cudaStreamNonBlocking);
        cudaEventCreateWithFlags(&s_evFork, cudaEventDisableTiming);
        cudaEventCreateWithFlags(&s_evJoin, cudaEventDisableTiming);
    }

    // fork: side stream builds the CSR (independent of GEMM chain)
    cudaEventRecord(s_evFork, 0);
    cudaStreamWaitEvent(s_sideStream, s_evFork, 0);
    zero_deg_kernel<<<(N_NODES + 255) / 256, 256, 0, s_sideStream>>>();
    hist_kernel<<<(N_EDGES + 255) / 256, 256, 0, s_sideStream>>>(edge);
    scan_kernel<<<1, 1024, 0, s_sideStream>>>();
    scatter_kernel<<<(N_EDGES + 255) / 256, 256, 0, s_sideStream>>>(edge);
    cudaEventRecord(s_evJoin, s_sideStream);

    // main stream: convert -> GEMM (fused hl/hr + fp16 h)
    convert_x_kernel<<<(N_NODES * FIN / 4 + 255) / 256, 256>>>(x);
    convert_w_kernel<<<(FIN * HF / 4 + 255) / 256, 256>>>(W);
    cudaFuncSetAttribute(gemm_mma_kernel, cudaFuncAttributeMaxDynamicSharedMemorySize, SMEM_BYTES);
    dim3 ggrid(HF / 128, (N_NODES + 127) / 128);     // (2, 391)
    gemm_mma_kernel<<<ggrid, 256, SMEM_BYTES>>>(a_l, a_r);

    // join, then aggregate
    cudaStreamWaitEvent(0, s_evJoin, 0);
    aggregate_kernel<<<(N_NODES * 2 * 32 + 255) / 256, 256>>>(out);
}

// round 17
// speedup vs baseline: 1.1018x; 1.0846x over previous
#include <cuda_runtime.h>
#include <cuda_bf16.h>
#include <cuda_fp16.h>
#include <cstdint>

#define N_NODES 50000
#define N_EDGES 800000
#define FIN 256
#define HF 256          // OUT_FEAT * NHEAD
#define NHEAD 4
#define ALPHA 0.2f

// ---------------- scratch (static device globals; no allocation) ----------------
__device__ __half g_hf16[(size_t)N_NODES * HF];        // 25.6 MB  h (only representation)
__device__ __nv_bfloat16 g_whi[FIN * HF];
__device__ __nv_bfloat16 g_wlo[FIN * HF];
__device__ float g_hl[N_NODES * NHEAD];
__device__ float g_hr[N_NODES * NHEAD];
__device__ int   g_deg[N_NODES];
__device__ int   g_off[N_NODES];
__device__ int   g_cur[N_NODES];
__device__ int   g_col[N_EDGES];

// ================= helpers =================
__device__ __forceinline__ uint32_t smem_u32(const void* p) {
    uint32_t a;
    asm("{ .reg .u64 t; cvta.to.shared.u64 t, %1; cvt.u32.u64 %0, t; }" : "=r"(a) : "l"(p));
    return a;
}
__device__ __forceinline__ void ldmat_x4(uint32_t* r, uint32_t addr) {
    asm volatile("ldmatrix.sync.aligned.m8n8.x4.shared.b16 {%0,%1,%2,%3}, [%4];"
                 : "=r"(r[0]), "=r"(r[1]), "=r"(r[2]), "=r"(r[3]) : "r"(addr));
}
__device__ __forceinline__ void ldmat_x4_t(uint32_t* r, uint32_t addr) {
    asm volatile("ldmatrix.sync.aligned.m8n8.x4.trans.shared.b16 {%0,%1,%2,%3}, [%4];"
                 : "=r"(r[0]), "=r"(r[1]), "=r"(r[2]), "=r"(r[3]) : "r"(addr));
}
__device__ __forceinline__ void mma_bf16(float* d, const uint32_t* a, uint32_t b0, uint32_t b1) {
    asm volatile(
        "mma.sync.aligned.m16n8k16.row.col.f32.bf16.bf16.f32 "
        "{%0,%1,%2,%3}, {%4,%5,%6,%7}, {%8,%9}, {%0,%1,%2,%3};"
        : "+f"(d[0]), "+f"(d[1]), "+f"(d[2]), "+f"(d[3])
        : "r"(a[0]), "r"(a[1]), "r"(a[2]), "r"(a[3]), "r"(b0), "r"(b1));
}

// ================= fp32 -> bf16 hi/lo split converter (W only) =================
__global__ void convert_w_kernel(const float* __restrict__ w) {
    const int i = blockIdx.x * blockDim.x + threadIdx.x;
    const int n4 = FIN * HF / 4;
    if (i >= n4) return;
    const float4 v = *(const float4*)(w + i * 4);
    __nv_bfloat162 h0, h1, l0, l1;
    h0.x = __float2bfloat16(v.x); h0.y = __float2bfloat16(v.y);
    h1.x = __float2bfloat16(v.z); h1.y = __float2bfloat16(v.w);
    l0.x = __float2bfloat16(v.x - __bfloat162float(h0.x));
    l0.y = __float2bfloat16(v.y - __bfloat162float(h0.y));
    l1.x = __float2bfloat16(v.z - __bfloat162float(h1.x));
    l1.y = __float2bfloat16(v.w - __bfloat162float(h1.y));
    uint2 hv, lv;
    hv.x = *(uint32_t*)&h0; hv.y = *(uint32_t*)&h1;
    lv.x = *(uint32_t*)&l0; lv.y = *(uint32_t*)&l1;
    *(uint2*)(g_whi + i * 4) = hv;
    *(uint2*)(g_wlo + i * 4) = lv;
}

// ================= GEMM: h = x @ W via split-bf16 mma.sync =================
// CTA tile 128(m) x 128(n), K chunks of 64. 8 warps = 4(m) x 2(n), warp tile 32x64.
// A converted fp32 -> bf16 hi/lo inline during smem fill (no g_xhi/g_xlo pass).
// Fused epilogue: fp16 h stores + hl/hr (warp's 64 cols = one head; shfl reduce).
#define AS_STRIDE 72
#define BS_STRIDE 136
#define A_BUF (128 * AS_STRIDE)
#define B_BUF (64 * BS_STRIDE)
#define SMEM_ELEMS (2 * (A_BUF + B_BUF))
#define SMEM_BYTES (SMEM_ELEMS * 2)  // 71680 B

__global__ void __launch_bounds__(256, 2) gemm_mma_kernel(const float* __restrict__ x,
                                                          const float* __restrict__ a_l,
                                                          const float* __restrict__ a_r) {
    extern __shared__ __nv_bfloat16 sm[];
    __nv_bfloat16* Ah = sm;
    __nv_bfloat16* Al = sm + A_BUF;
    __nv_bfloat16* Bh = sm + 2 * A_BUF;
    __nv_bfloat16* Bl = sm + 2 * A_BUF + B_BUF;

    const int tid = threadIdx.x;
    const int lane = tid & 31;
    const int warp = tid >> 5;
    const int warp_m = warp & 3;
    const int warp_n = warp >> 2;
    const int rowBase = blockIdx.y * 128;
    const int colBase = blockIdx.x * 128;

    float acc[2][8][4];
#pragma unroll
    for (int i = 0; i < 2; i++)
#pragma unroll
        for (int j = 0; j < 8; j++)
#pragma unroll
            for (int k = 0; k < 4; k++) acc[i][j][k] = 0.0f;

    const uint32_t sbase = smem_u32(sm);
    const uint32_t ah_b = sbase;
    const uint32_t al_b = sbase + A_BUF * 2;
    const uint32_t bh_b = sbase + 4 * A_BUF;
    const uint32_t bl_b = sbase + 4 * A_BUF + B_BUF * 2;

    for (int chunk = 0; chunk < 4; chunk++) {
        const int k0 = chunk * 64;
        // ---- A chunk: 128 rows x 64 k fp32, convert inline to hi/lo bf16 ----
        // 128*64 floats = 2048 float4; 8 per thread.
#pragma unroll
        for (int i = 0; i < 8; i++) {
            const int p = tid + i * 256;            // 0..2047
            const int row = p >> 4, seg = p & 15;   // 16 float4-segs per row
            const int gr = rowBase + row;
            float4 v = make_float4(0.f, 0.f, 0.f, 0.f);
            if (gr < N_NODES) v = *(const float4*)(x + (size_t)gr * FIN + k0 + seg * 4);
            __nv_bfloat162 h0, h1, l0, l1;
            h0.x = __float2bfloat16(v.x); h0.y = __float2bfloat16(v.y);
            h1.x = __float2bfloat16(v.z); h1.y = __float2bfloat16(v.w);
            l0.x = __float2bfloat16(v.x - __bfloat162float(h0.x));
            l0.y = __float2bfloat16(v.y - __bfloat162float(h0.y));
            l1.x = __float2bfloat16(v.z - __bfloat162float(h1.x));
            l1.y = __float2bfloat16(v.w - __bfloat162float(h1.y));
            uint2 hv, lv;
            hv.x = *(uint32_t*)&h0; hv.y = *(uint32_t*)&h1;
            lv.x = *(uint32_t*)&l0; lv.y = *(uint32_t*)&l1;
            *(uint2*)(Ah + row * AS_STRIDE + seg * 4) = hv;
            *(uint2*)(Al + row * AS_STRIDE + seg * 4) = lv;
        }
        // ---- B chunk: 64 k-rows x 128 n bf16 (hi & lo, pre-converted) ----
#pragma unroll
        for (int i = 0; i < 4; i++) {
            const int p = tid + i * 256;
            const int kk = p >> 4, c = p & 15;
            const size_t goff = (size_t)(k0 + kk) * HF + colBase + c * 8;
            *(uint4*)(Bh + kk * BS_STRIDE + c * 8) = *(const uint4*)(g_whi + goff);
            *(uint4*)(Bl + kk * BS_STRIDE + c * 8) = *(const uint4*)(g_wlo + goff);
        }
        __syncthreads();

#pragma unroll
        for (int ks = 0; ks < 4; ks++) {
            const int kk = ks * 16;
            uint32_t ahf[2][4], alf[2][4];
#pragma unroll
            for (int mt = 0; mt < 2; mt++) {
                const int r = warp_m * 32 + mt * 16 + (lane & 15);
                const uint32_t off = (uint32_t)(r * AS_STRIDE + kk + (lane >> 4) * 8) * 2;
                ldmat_x4(ahf[mt], ah_b + off);
                ldmat_x4(alf[mt], al_b + off);
            }
            uint32_t bhf[4][4], blf[4][4];
#pragma unroll
            for (int nb = 0; nb < 4; nb++) {
                const int r = kk + (lane & 15);
                const int n = warp_n * 64 + nb * 16 + (lane >> 4) * 8;
                const uint32_t off = (uint32_t)(r * BS_STRIDE + n) * 2;
                ldmat_x4_t(bhf[nb], bh_b + off);
                ldmat_x4_t(blf[nb], bl_b + off);
            }
#pragma unroll
            for (int mt = 0; mt < 2; mt++)
#pragma unroll
                for (int nt = 0; nt < 8; nt++) {
                    const int nb = nt >> 1, hh = (nt & 1) * 2;
                    mma_bf16(acc[mt][nt], ahf[mt], bhf[nb][hh], bhf[nb][hh + 1]);
                    mma_bf16(acc[mt][nt], ahf[mt], blf[nb][hh], blf[nb][hh + 1]);
                    mma_bf16(acc[mt][nt], alf[mt], bhf[nb][hh], bhf[nb][hh + 1]);
                }
        }
        __syncthreads();
    }

    const int g = lane >> 2, t = lane & 3;
    const int head = (colBase >> 6) + warp_n;     // this warp's 64 cols = one head

#pragma unroll
    for (int mt = 0; mt < 2; mt++) {
#pragma unroll
        for (int rh = 0; rh < 2; rh++) {
            const int r = rowBase + warp_m * 32 + mt * 16 + rh * 8 + g;
            float sl = 0.f, sr = 0.f;
#pragma unroll
            for (int nt = 0; nt < 8; nt++) {
                const int col = colBase + warp_n * 64 + nt * 8 + t * 2;
                const float v0 = acc[mt][nt][rh * 2 + 0];
                const float v1 = acc[mt][nt][rh * 2 + 1];
                if (r < N_NODES)
                    *(__half2*)(g_hf16 + (size_t)r * HF + col) = __floats2half2_rn(v0, v1);
                sl = fmaf(v0, a_l[col], sl); sl = fmaf(v1, a_l[col + 1], sl);
                sr = fmaf(v0, a_r[col], sr); sr = fmaf(v1, a_r[col + 1], sr);
            }
            sl += __shfl_xor_sync(0xffffffffu, sl, 1);
            sl += __shfl_xor_sync(0xffffffffu, sl, 2);
            sr += __shfl_xor_sync(0xffffffffu, sr, 1);
            sr += __shfl_xor_sync(0xffffffffu, sr, 2);
            if (t == 0 && r < N_NODES) {
                g_hl[r * NHEAD + head] = sl;
                g_hr[r * NHEAD + head] = sr;
            }
        }
    }
}

// ---------------- CSR build ----------------
__global__ void zero_deg_kernel() {
    int i = blockIdx.x * blockDim.x + threadIdx.x;
    if (i < N_NODES) g_deg[i] = 0;
}
__global__ void hist_kernel(const int* __restrict__ edge) {
    int i = blockIdx.x * blockDim.x + threadIdx.x;
    if (i < N_EDGES) atomicAdd(&g_deg[edge[i]], 1);
}
__global__ void scan_kernel() {
    __shared__ int partial[1024];
    const int t = threadIdx.x;
    const int CH = (N_NODES + 1023) / 1024;
    int beg = t * CH;
    int end = beg + CH; if (end > N_NODES) end = N_NODES;
    int s = 0;
    for (int i = beg; i < end; i++) s += g_deg[i];
    partial[t] = s;
    __syncthreads();
    for (int off = 1; off < 1024; off <<= 1) {
        int v = (t >= off) ? partial[t - off] : 0;
        __syncthreads();
        partial[t] += v;
        __syncthreads();
    }
    int run = (t == 0) ? 0 : partial[t - 1];
    for (int i = beg; i < end; i++) {
        g_off[i] = run;
        g_cur[i] = run;
        run += g_deg[i];
    }
}
__global__ void scatter_kernel(const int* __restrict__ edge) {
    int i = blockIdx.x * blockDim.x + threadIdx.x;
    if (i < N_EDGES) {
        int r = edge[i];
        int c = edge[N_EDGES + i];
        int pos = atomicAdd(&g_cur[r], 1);
        g_col[pos] = c;
    }
}

// ---------------- aggregation: 2 warps/node, fp16 gathers, 2-edge batch ----------------
__global__ void aggregate_kernel(float* __restrict__ out) {
    const int gw = (blockIdx.x * blockDim.x + threadIdx.x) >> 5;
    const int node = gw >> 1;
    if (node >= N_NODES) return;
    const int half = gw & 1;
    const int lane = threadIdx.x & 31;
    const int fbase = half * 128 + lane * 4;      // this lane's 4 features
    const int head = fbase >> 6;                  // 0..3 (16 lanes per head)

    const int start = g_off[node];
    const int d = g_deg[node];
    const float hlh = g_hl[node * NHEAD + head];

    float denom = 0.f;
    float a0 = 0.f, a1 = 0.f, a2 = 0.f, a3 = 0.f;

    int k = 0;
    for (; k + 2 <= d; k += 2) {
        const int c0 = g_col[start + k + 0];
        const int c1 = g_col[start + k + 1];
        float e0 = hlh + __ldg(g_hr + (size_t)c0 * NHEAD + head);
        float e1 = hlh + __ldg(g_hr + (size_t)c1 * NHEAD + head);
        e0 = e0 > 0.f ? e0 : ALPHA * e0;
        e1 = e1 > 0.f ? e1 : ALPHA * e1;
        const float w0 = __expf(e0), w1 = __expf(e1);
        denom += w0 + w1;
        const uint2 r0 = *(const uint2*)(g_hf16 + (size_t)c0 * HF + fbase);
        const uint2 r1 = *(const uint2*)(g_hf16 + (size_t)c1 * HF + fbase);
        const float2 u0 = __half22float2(*(const __half2*)&r0.x);
        const float2 u1 = __half22float2(*(const __half2*)&r0.y);
        const float2 u2 = __half22float2(*(const __half2*)&r1.x);
        const float2 u3 = __half22float2(*(const __half2*)&r1.y);
        a0 = fmaf(w0, u0.x, a0); a1 = fmaf(w0, u0.y, a1);
        a2 = fmaf(w0, u1.x, a2); a3 = fmaf(w0, u1.y, a3);
        a0 = fmaf(w1, u2.x, a0); a1 = fmaf(w1, u2.y, a1);
        a2 = fmaf(w1, u3.x, a2); a3 = fmaf(w1, u3.y, a3);
    }
    if (k < d) {
        const int c = g_col[start + k];
        float e = hlh + __ldg(g_hr + (size_t)c * NHEAD + head);
        e = e > 0.f ? e : ALPHA * e;
        const float w = __expf(e);
        denom += w;
        const uint2 r = *(const uint2*)(g_hf16 + (size_t)c * HF + fbase);
        const float2 u0 = __half22float2(*(const __half2*)&r.x);
        const float2 u1 = __half22float2(*(const __half2*)&r.y);
        a0 = fmaf(w, u0.x, a0); a1 = fmaf(w, u0.y, a1);
        a2 = fmaf(w, u1.x, a2); a3 = fmaf(w, u1.y, a3);
    }
    const float inv = 1.0f / fmaxf(denom, 1e-16f);
    *(float4*)(out + (size_t)node * HF + fbase) =
        make_float4(a0 * inv, a1 * inv, a2 * inv, a3 * inv);
}

// ---------------- launch: fork CSR build onto a side stream ----------------
static cudaStream_t s_sideStream = nullptr;
static cudaEvent_t  s_evFork = nullptr;
static cudaEvent_t  s_evJoin = nullptr;

extern "C" void kernel_launch(void* const* d_in, const int* in_sizes, int n_in,
                              void* d_out, int out_size) {
    const float* x    = (const float*)d_in[0];
    const int*   edge = (const int*)d_in[1];     // int32: [2, E] (rows; cols)
    const float* W    = (const float*)d_in[2];
    const float* a_l  = (const float*)d_in[3];
    const float* a_r  = (const float*)d_in[4];
    float* out = (float*)d_out;

    if (s_sideStream == nullptr) {               // first call is outside graph capture
        cudaStreamCreateWithFlags(&s_sideStream, cudaStreamNonBlocking);
        cudaEventCreateWithFlags(&s_evFork, cudaEventDisableTiming);
        cudaEventCreateWithFlags(&s_evJoin, cudaEventDisableTiming);
    }

    // fork: side stream builds the CSR (independent of GEMM chain)
    cudaEventRecord(s_evFork, 0);
    cudaStreamWaitEvent(s_sideStream, s_evFork, 0);
    zero_deg_kernel<<<(N_NODES + 255) / 256, 256, 0, s_sideStream>>>();
    hist_kernel<<<(N_EDGES + 255) / 256, 256, 0, s_sideStream>>>(edge);
    scan_kernel<<<1, 1024, 0, s_sideStream>>>();
    scatter_kernel<<<(N_EDGES + 255) / 256, 256, 0, s_sideStream>>>(edge);
    cudaEventRecord(s_evJoin, s_sideStream);

    // main stream: convert W -> GEMM (inline A convert + fused hl/hr + fp16 h)
    convert_w_kernel<<<(FIN * HF / 4 + 255) / 256, 256>>>(W);
    cudaFuncSetAttribute(gemm_mma_kernel, cudaFuncAttributeMaxDynamicSharedMemorySize, SMEM_BYTES);
    dim3 ggrid(HF / 128, (N_NODES + 127) / 128);     // (2, 391)
    gemm_mma_kernel<<<ggrid, 256, SMEM_BYTES>>>(x, a_l, a_r);

    // join, then aggregate
    cudaStreamWaitEvent(0, s_evJoin, 0);
    aggregate_kernel<<<(N_NODES * 2 * 32 + 255) / 256, 256>>>(out);
}